// round 13
// baseline (speedup 1.0000x reference)
#include <cuda_runtime.h>
#include <cuda_fp16.h>
#include <cuda_fp8.h>
#include <cstdint>

#define BN 4
#define NN 4096
#define CC 256
#define DD 32
#define OUT_E (4*64*64*256)
#define PSCALE 4096.0f

// Scratch (device globals -> no allocations)
__device__ __half   g_qh [BN * NN * DD];
__device__ __half   g_kh [BN * NN * DD];
__device__ uint8_t  g_v8t[(long)BN * CC * NN];   // V transposed: [b][c][j], e4m3
__device__ float    g_s  [BN * NN];              // 1/rowsum
__device__ uint8_t  g_p8 [(long)BN * NN * NN];   // P' = att*4096, e4m3 (64 MB)

// ---------------------------------------------------------------------------
// helpers
// ---------------------------------------------------------------------------
__device__ __forceinline__ uint32_t smem_u32(const void* p) {
    return (uint32_t)__cvta_generic_to_shared(p);
}
__device__ __forceinline__ void ldsm4(uint32_t* r, uint32_t addr) {
    asm volatile("ldmatrix.sync.aligned.m8n8.x4.shared.b16 {%0,%1,%2,%3}, [%4];"
                 : "=r"(r[0]), "=r"(r[1]), "=r"(r[2]), "=r"(r[3]) : "r"(addr));
}
__device__ __forceinline__ void mma_f16(float* c, const uint32_t* a,
                                        uint32_t b0, uint32_t b1) {
    asm volatile("mma.sync.aligned.m16n8k16.row.col.f32.f16.f16.f32 "
                 "{%0,%1,%2,%3}, {%4,%5,%6,%7}, {%8,%9}, {%0,%1,%2,%3};"
                 : "+f"(c[0]), "+f"(c[1]), "+f"(c[2]), "+f"(c[3])
                 : "r"(a[0]), "r"(a[1]), "r"(a[2]), "r"(a[3]), "r"(b0), "r"(b1));
}
__device__ __forceinline__ void mma_f8(float* c, const uint32_t* a,
                                       uint32_t b0, uint32_t b1) {
    asm volatile("mma.sync.aligned.m16n8k32.row.col.f32.e4m3.e4m3.f32 "
                 "{%0,%1,%2,%3}, {%4,%5,%6,%7}, {%8,%9}, {%0,%1,%2,%3};"
                 : "+f"(c[0]), "+f"(c[1]), "+f"(c[2]), "+f"(c[3])
                 : "r"(a[0]), "r"(a[1]), "r"(a[2]), "r"(a[3]), "r"(b0), "r"(b1));
}
__device__ __forceinline__ unsigned short f2_to_e4m3x2(float lo, float hi) {
    return (unsigned short)__nv_cvt_float2_to_fp8x2(make_float2(lo, hi),
                                                    __NV_SATFINITE, __NV_E4M3);
}
#define CP16(dst, src) \
    asm volatile("cp.async.cg.shared.global [%0], [%1], 16;" :: "r"(dst), "l"(src))
#define CP_COMMIT() asm volatile("cp.async.commit_group;" ::: "memory")
#define CP_WAIT(n)  asm volatile("cp.async.wait_group %0;" :: "n"(n) : "memory")

// ---------------------------------------------------------------------------
// Kernel 1: fused q,k,v projections via fp16 HMMA (unchanged from R12).
// ---------------------------------------------------------------------------
#define VK_X_OFF   0
#define VK_W_OFF   5120
#define VK_QK_OFF  25600
#define VK_T_OFF   5120
__global__ void __launch_bounds__(256, 2) qkv16_kernel(
    const float* __restrict__ x,
    const float* __restrict__ Wq, const float* __restrict__ bq,
    const float* __restrict__ Wk, const float* __restrict__ bk,
    const float* __restrict__ Wv, const float* __restrict__ bv)
{
    __shared__ __align__(16) char sm[30720];
    const uint32_t sb = smem_u32(sm);
    int row0 = blockIdx.x * 64;
    int tid  = threadIdx.x;
    int lane = tid & 31, warp = tid >> 5;
    int wm = warp & 1, wn = warp >> 1;

    float acc[2][8][4];
    float aqk[2][2][4];
#pragma unroll
    for (int mt = 0; mt < 2; mt++) {
#pragma unroll
        for (int nt = 0; nt < 8; nt++)
#pragma unroll
            for (int u = 0; u < 4; u++) acc[mt][nt][u] = 0.f;
#pragma unroll
        for (int nt = 0; nt < 2; nt++)
#pragma unroll
            for (int u = 0; u < 4; u++) aqk[mt][nt][u] = 0.f;
    }

    for (int kc = 0; kc < CC; kc += 32) {
        __syncthreads();
        {
            int r = tid >> 2, kq = (tid & 3) * 8;
            float4 xa = *(const float4*)&x[(long)(row0 + r) * CC + kc + kq];
            float4 xb = *(const float4*)&x[(long)(row0 + r) * CC + kc + kq + 4];
            __half2 h[4];
            h[0] = __floats2half2_rn(xa.x, xa.y);
            h[1] = __floats2half2_rn(xa.z, xa.w);
            h[2] = __floats2half2_rn(xb.x, xb.y);
            h[3] = __floats2half2_rn(xb.z, xb.w);
            *(uint4*)(sm + VK_X_OFF + r * 80 + kq * 2) = *(uint4*)h;
        }
#pragma unroll
        for (int p = 0; p < 32; p++) {
            int kk = p, n = tid;
            float wv_ = Wv[(long)(kc + kk) * CC + n];
            *(__half*)(sm + VK_W_OFF + n * 80 + kk * 2) = __float2half_rn(wv_);
        }
        {
            int n = tid & 63, kb = (tid >> 6) * 8;
#pragma unroll
            for (int k2 = 0; k2 < 8; k2++) {
                int kk = kb + k2;
                float wv_ = (n < 32) ? Wq[(long)(kc + kk) * DD + n]
                                     : Wk[(long)(kc + kk) * DD + (n - 32)];
                *(__half*)(sm + VK_QK_OFF + n * 80 + kk * 2) = __float2half_rn(wv_);
            }
        }
        __syncthreads();

        uint32_t af[2][2][4];
#pragma unroll
        for (int mt = 0; mt < 2; mt++) {
            uint32_t abase = sb + VK_X_OFF
                + (wm * 32 + mt * 16 + (lane & 7) + ((lane >> 3) & 1) * 8) * 80
                + (lane >> 4) * 16;
            ldsm4(af[mt][0], abase);
            ldsm4(af[mt][1], abase + 32);
        }
#pragma unroll
        for (int nt = 0; nt < 8; nt++) {
            uint32_t bf[4];
            uint32_t bbase = sb + VK_W_OFF
                + (wn * 64 + nt * 8 + (lane & 7)) * 80 + (lane >> 3) * 16;
            ldsm4(bf, bbase);
            mma_f16(acc[0][nt], af[0][0], bf[0], bf[1]);
            mma_f16(acc[0][nt], af[0][1], bf[2], bf[3]);
            mma_f16(acc[1][nt], af[1][0], bf[0], bf[1]);
            mma_f16(acc[1][nt], af[1][1], bf[2], bf[3]);
        }
#pragma unroll
        for (int nt = 0; nt < 2; nt++) {
            uint32_t bf[4];
            uint32_t bbase = sb + VK_QK_OFF
                + (wn * 16 + nt * 8 + (lane & 7)) * 80 + (lane >> 3) * 16;
            ldsm4(bf, bbase);
            mma_f16(aqk[0][nt], af[0][0], bf[0], bf[1]);
            mma_f16(aqk[0][nt], af[0][1], bf[2], bf[3]);
            mma_f16(aqk[1][nt], af[1][0], bf[0], bf[1]);
            mma_f16(aqk[1][nt], af[1][1], bf[2], bf[3]);
        }
    }

    // q/k epilogue
#pragma unroll
    for (int mt = 0; mt < 2; mt++) {
#pragma unroll
        for (int nt = 0; nt < 2; nt++) {
            int r = wm * 32 + mt * 16 + (lane >> 2);
            int gcol = wn * 16 + nt * 8 + ((lane & 3) << 1);
            int isq = gcol < 32;
            int cc = isq ? gcol : gcol - 32;
            const float* bb_ = isq ? bq : bk;
            __half* dst = isq ? g_qh : g_kh;
            float b0 = bb_[cc], b1 = bb_[cc + 1];
            *(__half2*)&dst[(long)(row0 + r) * DD + cc] =
                __floats2half2_rn(aqk[mt][nt][0] + b0, aqk[mt][nt][1] + b1);
            *(__half2*)&dst[(long)(row0 + r + 8) * DD + cc] =
                __floats2half2_rn(aqk[mt][nt][2] + b0, aqk[mt][nt][3] + b1);
        }
    }

    __syncthreads();

    uint8_t* t8 = (uint8_t*)(sm + VK_T_OFF);
#pragma unroll
    for (int mt = 0; mt < 2; mt++) {
        int r = wm * 32 + mt * 16 + (lane >> 2);
#pragma unroll
        for (int nt = 0; nt < 8; nt++) {
            int c = wn * 64 + nt * 8 + ((lane & 3) << 1);
            float b0 = bv[c], b1 = bv[c + 1];
            unsigned short pa = f2_to_e4m3x2(acc[mt][nt][0] + b0, acc[mt][nt][1] + b1);
            unsigned short pb = f2_to_e4m3x2(acc[mt][nt][2] + b0, acc[mt][nt][3] + b1);
            t8[c * 80 + r]           = (uint8_t)(pa & 0xff);
            t8[(c + 1) * 80 + r]     = (uint8_t)(pa >> 8);
            t8[c * 80 + r + 8]       = (uint8_t)(pb & 0xff);
            t8[(c + 1) * 80 + r + 8] = (uint8_t)(pb >> 8);
        }
    }
    __syncthreads();

    int bb = row0 / NN;
    int jj = row0 % NN;
    uint8_t* vt = g_v8t + (long)bb * CC * NN;
#pragma unroll
    for (int p = 0; p < 4; p++) {
        int e = tid + p * 256;
        int c = e >> 2, j16 = (e & 3) * 16;
        uint4 v4 = *(uint4*)(sm + VK_T_OFF + c * 80 + j16);
        *(uint4*)&vt[(long)c * NN + jj + j16] = v4;
    }
}

// ---------------------------------------------------------------------------
// Kernel 2: row sums of exp(Q.K^T) -> g_s = 1/s (unchanged from R12).
// ---------------------------------------------------------------------------
#define SK_Q_OFF  0
#define SK_K_OFF  2560
#define SK_KSTG   10240
#define SK_SR_OFF (2560 + 3*10240)
__global__ void __launch_bounds__(128) sum_kernel()
{
    __shared__ __align__(16) char sm[33792];
    const uint32_t sb = smem_u32(sm);
    int tid = threadIdx.x, lane = tid & 31, w = tid >> 5;
    int b = blockIdx.y, i0 = blockIdx.x * 32;
    const __half* qg = g_qh + ((long)b * NN + i0) * DD;
    const __half* kg = g_kh + (long)b * NN * DD;

    {
        int r = tid >> 2, ch = tid & 3;
        *(uint4*)(sm + SK_Q_OFF + r * 80 + ch * 16) = *(const uint4*)(qg + r * DD + ch * 8);
    }
    {
        uint32_t kst = sb + SK_K_OFF;
#pragma unroll
        for (int p = 0; p < 4; p++) {
            int idx = tid + p * 128;
            int r = idx >> 2, ch = idx & 3;
            CP16(kst + r * 80 + ch * 16, kg + r * DD + ch * 8);
        }
        CP_COMMIT();
    }
    __syncthreads();

    uint32_t qf[2][2][4];
#pragma unroll
    for (int mt = 0; mt < 2; mt++) {
        uint32_t base = sb + SK_Q_OFF
            + (mt * 16 + (lane & 7) + ((lane >> 3) & 1) * 8) * 80 + (lane >> 4) * 16;
        ldsm4(qf[mt][0], base);
        ldsm4(qf[mt][1], base + 32);
    }

    float s[4] = {0.f, 0.f, 0.f, 0.f};
    for (int t = 0; t < 32; t++) {
        if (t + 1 < 32) {
            uint32_t kst = sb + SK_K_OFF + ((t + 1) % 3) * SK_KSTG;
            const __half* src = kg + (t + 1) * 128 * DD;
#pragma unroll
            for (int p = 0; p < 4; p++) {
                int idx = tid + p * 128;
                int r = idx >> 2, ch = idx & 3;
                CP16(kst + r * 80 + ch * 16, src + r * DD + ch * 8);
            }
        }
        CP_COMMIT();
        CP_WAIT(1);
        __syncthreads();

        uint32_t kst = sb + SK_K_OFF + (t % 3) * SK_KSTG;
        uint32_t bbase = kst + (w * 32 + (lane & 7)) * 80 + (lane >> 3) * 16;
#pragma unroll
        for (int nt = 0; nt < 4; nt++) {
            uint32_t bf[4];
            ldsm4(bf, bbase + nt * 8 * 80);
#pragma unroll
            for (int mt = 0; mt < 2; mt++) {
                float c[4] = {0.f, 0.f, 0.f, 0.f};
                mma_f16(c, qf[mt][0], bf[0], bf[1]);
                mma_f16(c, qf[mt][1], bf[2], bf[3]);
                s[mt * 2]     += __expf(c[0]) + __expf(c[1]);
                s[mt * 2 + 1] += __expf(c[2]) + __expf(c[3]);
            }
        }
    }
#pragma unroll
    for (int k = 0; k < 4; k++) {
        s[k] += __shfl_xor_sync(0xffffffffu, s[k], 1);
        s[k] += __shfl_xor_sync(0xffffffffu, s[k], 2);
    }
    float* sred = (float*)(sm + SK_SR_OFF);
    if ((lane & 3) == 0) {
        int r0 = lane >> 2;
        sred[(r0     ) * 4 + w] = s[0];
        sred[(r0 + 8 ) * 4 + w] = s[1];
        sred[(r0 + 16) * 4 + w] = s[2];
        sred[(r0 + 24) * 4 + w] = s[3];
    }
    __syncthreads();
    if (tid < 32) {
        float tot = sred[tid * 4] + sred[tid * 4 + 1] + sred[tid * 4 + 2] + sred[tid * 4 + 3];
        g_s[b * NN + i0 + tid] = 1.0f / tot;
    }
}

// ---------------------------------------------------------------------------
// Kernel 3: E -> att (f32, streamed) + P' (e4m3 x4096).  High-occupancy.
//  32 i-rows per CTA, 128 threads, j-tiles of 128, 3-stage cp.async.
// ---------------------------------------------------------------------------
__global__ void __launch_bounds__(128) attE_kernel(float* __restrict__ att)
{
    __shared__ __align__(16) char sm[33280];
    const uint32_t sb = smem_u32(sm);
    int tid = threadIdx.x, lane = tid & 31, w = tid >> 5;
    int b = blockIdx.y, i0 = blockIdx.x * 32;
    const __half* qg = g_qh + ((long)b * NN + i0) * DD;
    const __half* kg = g_kh + (long)b * NN * DD;

    {
        int r = tid >> 2, ch = tid & 3;
        *(uint4*)(sm + SK_Q_OFF + r * 80 + ch * 16) = *(const uint4*)(qg + r * DD + ch * 8);
    }
    {
        uint32_t kst = sb + SK_K_OFF;
#pragma unroll
        for (int p = 0; p < 4; p++) {
            int idx = tid + p * 128;
            int r = idx >> 2, ch = idx & 3;
            CP16(kst + r * 80 + ch * 16, kg + r * DD + ch * 8);
        }
        CP_COMMIT();
    }
    __syncthreads();

    uint32_t qf[2][2][4];
#pragma unroll
    for (int mt = 0; mt < 2; mt++) {
        uint32_t base = sb + SK_Q_OFF
            + (mt * 16 + (lane & 7) + ((lane >> 3) & 1) * 8) * 80 + (lane >> 4) * 16;
        ldsm4(qf[mt][0], base);
        ldsm4(qf[mt][1], base + 32);
    }
    float is_[4];
    {
        int r0 = lane >> 2;
        is_[0] = g_s[b * NN + i0 + r0];
        is_[1] = g_s[b * NN + i0 + r0 + 8];
        is_[2] = g_s[b * NN + i0 + r0 + 16];
        is_[3] = g_s[b * NN + i0 + r0 + 24];
    }

    float*   ab = att ? att + ((long)b * NN + i0) * NN : (float*)0;
    uint8_t* pb = g_p8 + ((long)b * NN + i0) * NN;

    for (int t = 0; t < 32; t++) {
        if (t + 1 < 32) {
            uint32_t kst = sb + SK_K_OFF + ((t + 1) % 3) * SK_KSTG;
            const __half* src = kg + (t + 1) * 128 * DD;
#pragma unroll
            for (int p = 0; p < 4; p++) {
                int idx = tid + p * 128;
                int r = idx >> 2, ch = idx & 3;
                CP16(kst + r * 80 + ch * 16, src + r * DD + ch * 8);
            }
        }
        CP_COMMIT();
        CP_WAIT(1);
        __syncthreads();

        uint32_t kst = sb + SK_K_OFF + (t % 3) * SK_KSTG;
        uint32_t bbase = kst + (w * 32 + (lane & 7)) * 80 + (lane >> 3) * 16;
        const long j0 = (long)t * 128;
#pragma unroll
        for (int nt = 0; nt < 4; nt++) {
            uint32_t bf[4];
            ldsm4(bf, bbase + nt * 8 * 80);
            long col = j0 + w * 32 + nt * 8 + ((lane & 3) << 1);
#pragma unroll
            for (int mt = 0; mt < 2; mt++) {
                float c[4] = {0.f, 0.f, 0.f, 0.f};
                mma_f16(c, qf[mt][0], bf[0], bf[1]);
                mma_f16(c, qf[mt][1], bf[2], bf[3]);
                float a0 = __expf(c[0]) * is_[mt * 2];
                float a1 = __expf(c[1]) * is_[mt * 2];
                float a2 = __expf(c[2]) * is_[mt * 2 + 1];
                float a3 = __expf(c[3]) * is_[mt * 2 + 1];
                int er = mt * 16 + (lane >> 2);
                *(unsigned short*)&pb[(long)er * NN + col] =
                    f2_to_e4m3x2(a0 * PSCALE, a1 * PSCALE);
                *(unsigned short*)&pb[(long)(er + 8) * NN + col] =
                    f2_to_e4m3x2(a2 * PSCALE, a3 * PSCALE);
                if (ab) {
                    __stcs((float2*)&ab[(long)er * NN + col], make_float2(a0, a1));
                    __stcs((float2*)&ab[(long)(er + 8) * NN + col], make_float2(a2, a3));
                }
            }
        }
    }
}

// ---------------------------------------------------------------------------
// Kernel 4: O = P' @ V^T (pure e4m3 QMMA GEMM); y = O*gamma/PSCALE + x.
//  64 i-rows x 256 cols per CTA, 8 warps (2i x 4c), K(j) tiles of 64, 2-stage.
// ---------------------------------------------------------------------------
#define AV_STG   25600     // per stage: P 64x80 (5120) + V 256x80 (20480)
#define AV_V_OFF 5120
__global__ void __launch_bounds__(256, 2) av8_kernel(
    const float* __restrict__ x, const float* __restrict__ gamma,
    float* __restrict__ y)
{
    extern __shared__ __align__(16) char sm[];
    const uint32_t sb = smem_u32(sm);
    const int tid  = threadIdx.x;
    const int lane = tid & 31, w = tid >> 5;
    const int avi = w & 1, avc = w >> 1;

    const int b  = blockIdx.y;
    const int i0 = blockIdx.x * 64;

    const uint8_t* pg  = g_p8 + ((long)b * NN + i0) * NN;
    const uint8_t* vtg = g_v8t + (long)b * CC * NN;

    // prolog: stages 0,1
#pragma unroll
    for (int st = 0; st < 2; st++) {
        uint32_t base = sb + st * AV_STG;
        {
            int r = tid >> 2, ch = tid & 3;
            CP16(base + r * 80 + ch * 16, pg + (long)r * NN + st * 64 + ch * 16);
        }
#pragma unroll
        for (int p = 0; p < 4; p++) {
            int idx = tid + p * 256;
            int c = idx >> 2, ch = idx & 3;
            CP16(base + AV_V_OFF + c * 80 + ch * 16, vtg + (long)c * NN + st * 64 + ch * 16);
        }
        CP_COMMIT();
    }

    float acc[2][8][4];
#pragma unroll
    for (int mt = 0; mt < 2; mt++)
#pragma unroll
        for (int nt = 0; nt < 8; nt++)
#pragma unroll
            for (int u = 0; u < 4; u++) acc[mt][nt][u] = 0.f;

    for (int t = 0; t < 64; t++) {
        CP_WAIT(1);
        __syncthreads();

        uint32_t stg = sb + (t & 1) * AV_STG;
        uint32_t pA  = stg
            + (avi * 32 + (lane & 7) + ((lane >> 3) & 1) * 8) * 80
            + ((lane >> 4) & 1) * 16;
        uint32_t af[2][2][4];
#pragma unroll
        for (int mt = 0; mt < 2; mt++) {
            ldsm4(af[mt][0], pA + mt * 16 * 80);
            ldsm4(af[mt][1], pA + mt * 16 * 80 + 32);
        }
        uint32_t vst = stg + AV_V_OFF;
#pragma unroll
        for (int kk = 0; kk < 2; kk++) {
#pragma unroll
            for (int ntg = 0; ntg < 4; ntg++) {
                uint32_t bv[4];
                uint32_t baddr = vst
                    + (avc * 64 + ntg * 16 + (lane & 7) + ((lane >> 4) & 1) * 8) * 80
                    + ((lane >> 3) & 1) * 16 + kk * 32;
                ldsm4(bv, baddr);
                mma_f8(acc[0][ntg * 2],     af[0][kk], bv[0], bv[1]);
                mma_f8(acc[0][ntg * 2 + 1], af[0][kk], bv[2], bv[3]);
                mma_f8(acc[1][ntg * 2],     af[1][kk], bv[0], bv[1]);
                mma_f8(acc[1][ntg * 2 + 1], af[1][kk], bv[2], bv[3]);
            }
        }
        __syncthreads();   // stage (t&1) fully consumed before refill

        if (t + 2 < 64) {
            uint32_t base = sb + (t & 1) * AV_STG;
            const int j0 = (t + 2) * 64;
            {
                int r = tid >> 2, ch = tid & 3;
                CP16(base + r * 80 + ch * 16, pg + (long)r * NN + j0 + ch * 16);
            }
#pragma unroll
            for (int p = 0; p < 4; p++) {
                int idx = tid + p * 256;
                int c = idx >> 2, ch = idx & 3;
                CP16(base + AV_V_OFF + c * 80 + ch * 16, vtg + (long)c * NN + j0 + ch * 16);
            }
        }
        CP_COMMIT();
    }

    // epilogue: y = acc*(gamma/PSCALE) + x
    const float g = gamma[0] * (1.0f / PSCALE);
    const float* xb = x + ((long)b * NN + i0) * CC;
    float* yb = y + ((long)b * NN + i0) * CC;
#pragma unroll
    for (int mt = 0; mt < 2; mt++) {
        int r0 = avi * 32 + mt * 16 + (lane >> 2);
#pragma unroll
        for (int nt = 0; nt < 8; nt++) {
            int c = avc * 64 + nt * 8 + ((lane & 3) << 1);
            float2 x0 = *(const float2*)&xb[(long)r0 * CC + c];
            float2 x1 = *(const float2*)&xb[(long)(r0 + 8) * CC + c];
            float2 o0, o1;
            o0.x = acc[mt][nt][0] * g + x0.x;  o0.y = acc[mt][nt][1] * g + x0.y;
            o1.x = acc[mt][nt][2] * g + x1.x;  o1.y = acc[mt][nt][3] * g + x1.y;
            *(float2*)&yb[(long)r0 * CC + c]       = o0;
            *(float2*)&yb[(long)(r0 + 8) * CC + c] = o1;
        }
    }
}

// ---------------------------------------------------------------------------
extern "C" void kernel_launch(void* const* d_in, const int* in_sizes, int n_in,
                              void* d_out, int out_size)
{
    const float* x     = (const float*)d_in[0];
    const float* Wq    = (const float*)d_in[1];
    const float* bq    = (const float*)d_in[2];
    const float* Wk    = (const float*)d_in[3];
    const float* bk    = (const float*)d_in[4];
    const float* Wv    = (const float*)d_in[5];
    const float* bv    = (const float*)d_in[6];
    const float* gamma = (const float*)d_in[7];
    float* y = (float*)d_out;

    const long ATT_E = (long)BN * NN * NN;
    float* att_out = 0;
    if ((long)out_size == (long)OUT_E + ATT_E) att_out = y + OUT_E;

    cudaFuncSetAttribute(av8_kernel, cudaFuncAttributeMaxDynamicSharedMemorySize,
                         2 * AV_STG);

    qkv16_kernel<<<BN * NN / 64, 256>>>(x, Wq, bq, Wk, bk, Wv, bv);
    sum_kernel<<<dim3(NN / 32, BN), 128>>>();
    attE_kernel<<<dim3(NN / 32, BN), 128>>>(att_out);
    av8_kernel<<<dim3(NN / 64, BN), 256, 2 * AV_STG>>>(x, gamma, y);
}

// round 14
// speedup vs baseline: 1.3069x; 1.3069x over previous
#include <cuda_runtime.h>
#include <cuda_fp16.h>
#include <cuda_fp8.h>
#include <cstdint>

#define BN 4
#define NN 4096
#define CC 256
#define DD 32
#define OUT_E (4*64*64*256)
#define PSCALE 4096.0f

// Scratch (device globals -> no allocations)
__device__ __half   g_qh [BN * NN * DD];
__device__ __half   g_kh [BN * NN * DD];
__device__ uint8_t  g_v8t[(long)BN * CC * NN];   // V transposed: [b][c][j], e4m3
__device__ float    g_s  [BN * NN];              // 1/rowsum
__device__ __half   g_w  [(long)BN * NN * NN];   // w = exp(e), fp16 (128 MB)

// ---------------------------------------------------------------------------
// helpers
// ---------------------------------------------------------------------------
__device__ __forceinline__ uint32_t smem_u32(const void* p) {
    return (uint32_t)__cvta_generic_to_shared(p);
}
__device__ __forceinline__ void ldsm4(uint32_t* r, uint32_t addr) {
    asm volatile("ldmatrix.sync.aligned.m8n8.x4.shared.b16 {%0,%1,%2,%3}, [%4];"
                 : "=r"(r[0]), "=r"(r[1]), "=r"(r[2]), "=r"(r[3]) : "r"(addr));
}
__device__ __forceinline__ void mma_f16(float* c, const uint32_t* a,
                                        uint32_t b0, uint32_t b1) {
    asm volatile("mma.sync.aligned.m16n8k16.row.col.f32.f16.f16.f32 "
                 "{%0,%1,%2,%3}, {%4,%5,%6,%7}, {%8,%9}, {%0,%1,%2,%3};"
                 : "+f"(c[0]), "+f"(c[1]), "+f"(c[2]), "+f"(c[3])
                 : "r"(a[0]), "r"(a[1]), "r"(a[2]), "r"(a[3]), "r"(b0), "r"(b1));
}
__device__ __forceinline__ void mma_f8(float* c, const uint32_t* a,
                                       uint32_t b0, uint32_t b1) {
    asm volatile("mma.sync.aligned.m16n8k32.row.col.f32.e4m3.e4m3.f32 "
                 "{%0,%1,%2,%3}, {%4,%5,%6,%7}, {%8,%9}, {%0,%1,%2,%3};"
                 : "+f"(c[0]), "+f"(c[1]), "+f"(c[2]), "+f"(c[3])
                 : "r"(a[0]), "r"(a[1]), "r"(a[2]), "r"(a[3]), "r"(b0), "r"(b1));
}
__device__ __forceinline__ unsigned short f2_to_e4m3x2(float lo, float hi) {
    return (unsigned short)__nv_cvt_float2_to_fp8x2(make_float2(lo, hi),
                                                    __NV_SATFINITE, __NV_E4M3);
}
#define CP16(dst, src) \
    asm volatile("cp.async.cg.shared.global [%0], [%1], 16;" :: "r"(dst), "l"(src))
#define CP_COMMIT() asm volatile("cp.async.commit_group;" ::: "memory")
#define CP_WAIT(n)  asm volatile("cp.async.wait_group %0;" :: "n"(n) : "memory")

// attn smem layout (bytes).
#define P_OFF     0                      // 64 x 80 fp8
#define W_OFF     5120                   // 3 stages x 64 x 144 fp16 (27648)
#define V_OFF     32768                  // 3 stages x 256 x 80 fp8 (61440)
#define ATT_OFF   94208                  // 64 x 72 f32 (18432)
#define SS_OFF    112640                 // 64 f32
#define SMEM_ATTN 112896
#define W_STAGE   9216
#define V_STAGE   20480
#define ATT_STRIDE 72

// ---------------------------------------------------------------------------
// Kernel 1: fused q,k,v projections via fp16 HMMA (unchanged from R12).
// ---------------------------------------------------------------------------
#define VK_X_OFF   0
#define VK_W_OFF   5120
#define VK_QK_OFF  25600
#define VK_T_OFF   5120
__global__ void __launch_bounds__(256, 2) qkv16_kernel(
    const float* __restrict__ x,
    const float* __restrict__ Wq, const float* __restrict__ bq,
    const float* __restrict__ Wk, const float* __restrict__ bk,
    const float* __restrict__ Wv, const float* __restrict__ bv)
{
    __shared__ __align__(16) char sm[30720];
    const uint32_t sb = smem_u32(sm);
    int row0 = blockIdx.x * 64;
    int tid  = threadIdx.x;
    int lane = tid & 31, warp = tid >> 5;
    int wm = warp & 1, wn = warp >> 1;

    float acc[2][8][4];
    float aqk[2][2][4];
#pragma unroll
    for (int mt = 0; mt < 2; mt++) {
#pragma unroll
        for (int nt = 0; nt < 8; nt++)
#pragma unroll
            for (int u = 0; u < 4; u++) acc[mt][nt][u] = 0.f;
#pragma unroll
        for (int nt = 0; nt < 2; nt++)
#pragma unroll
            for (int u = 0; u < 4; u++) aqk[mt][nt][u] = 0.f;
    }

    for (int kc = 0; kc < CC; kc += 32) {
        __syncthreads();
        {
            int r = tid >> 2, kq = (tid & 3) * 8;
            float4 xa = *(const float4*)&x[(long)(row0 + r) * CC + kc + kq];
            float4 xb = *(const float4*)&x[(long)(row0 + r) * CC + kc + kq + 4];
            __half2 h[4];
            h[0] = __floats2half2_rn(xa.x, xa.y);
            h[1] = __floats2half2_rn(xa.z, xa.w);
            h[2] = __floats2half2_rn(xb.x, xb.y);
            h[3] = __floats2half2_rn(xb.z, xb.w);
            *(uint4*)(sm + VK_X_OFF + r * 80 + kq * 2) = *(uint4*)h;
        }
#pragma unroll
        for (int p = 0; p < 32; p++) {
            int kk = p, n = tid;
            float wv_ = Wv[(long)(kc + kk) * CC + n];
            *(__half*)(sm + VK_W_OFF + n * 80 + kk * 2) = __float2half_rn(wv_);
        }
        {
            int n = tid & 63, kb = (tid >> 6) * 8;
#pragma unroll
            for (int k2 = 0; k2 < 8; k2++) {
                int kk = kb + k2;
                float wv_ = (n < 32) ? Wq[(long)(kc + kk) * DD + n]
                                     : Wk[(long)(kc + kk) * DD + (n - 32)];
                *(__half*)(sm + VK_QK_OFF + n * 80 + kk * 2) = __float2half_rn(wv_);
            }
        }
        __syncthreads();

        uint32_t af[2][2][4];
#pragma unroll
        for (int mt = 0; mt < 2; mt++) {
            uint32_t abase = sb + VK_X_OFF
                + (wm * 32 + mt * 16 + (lane & 7) + ((lane >> 3) & 1) * 8) * 80
                + (lane >> 4) * 16;
            ldsm4(af[mt][0], abase);
            ldsm4(af[mt][1], abase + 32);
        }
#pragma unroll
        for (int nt = 0; nt < 8; nt++) {
            uint32_t bf[4];
            uint32_t bbase = sb + VK_W_OFF
                + (wn * 64 + nt * 8 + (lane & 7)) * 80 + (lane >> 3) * 16;
            ldsm4(bf, bbase);
            mma_f16(acc[0][nt], af[0][0], bf[0], bf[1]);
            mma_f16(acc[0][nt], af[0][1], bf[2], bf[3]);
            mma_f16(acc[1][nt], af[1][0], bf[0], bf[1]);
            mma_f16(acc[1][nt], af[1][1], bf[2], bf[3]);
        }
#pragma unroll
        for (int nt = 0; nt < 2; nt++) {
            uint32_t bf[4];
            uint32_t bbase = sb + VK_QK_OFF
                + (wn * 16 + nt * 8 + (lane & 7)) * 80 + (lane >> 3) * 16;
            ldsm4(bf, bbase);
            mma_f16(aqk[0][nt], af[0][0], bf[0], bf[1]);
            mma_f16(aqk[0][nt], af[0][1], bf[2], bf[3]);
            mma_f16(aqk[1][nt], af[1][0], bf[0], bf[1]);
            mma_f16(aqk[1][nt], af[1][1], bf[2], bf[3]);
        }
    }

    // q/k epilogue
#pragma unroll
    for (int mt = 0; mt < 2; mt++) {
#pragma unroll
        for (int nt = 0; nt < 2; nt++) {
            int r = wm * 32 + mt * 16 + (lane >> 2);
            int gcol = wn * 16 + nt * 8 + ((lane & 3) << 1);
            int isq = gcol < 32;
            int cc = isq ? gcol : gcol - 32;
            const float* bb_ = isq ? bq : bk;
            __half* dst = isq ? g_qh : g_kh;
            float b0 = bb_[cc], b1 = bb_[cc + 1];
            *(__half2*)&dst[(long)(row0 + r) * DD + cc] =
                __floats2half2_rn(aqk[mt][nt][0] + b0, aqk[mt][nt][1] + b1);
            *(__half2*)&dst[(long)(row0 + r + 8) * DD + cc] =
                __floats2half2_rn(aqk[mt][nt][2] + b0, aqk[mt][nt][3] + b1);
        }
    }

    __syncthreads();

    uint8_t* t8 = (uint8_t*)(sm + VK_T_OFF);
#pragma unroll
    for (int mt = 0; mt < 2; mt++) {
        int r = wm * 32 + mt * 16 + (lane >> 2);
#pragma unroll
        for (int nt = 0; nt < 8; nt++) {
            int c = wn * 64 + nt * 8 + ((lane & 3) << 1);
            float b0 = bv[c], b1 = bv[c + 1];
            unsigned short pa = f2_to_e4m3x2(acc[mt][nt][0] + b0, acc[mt][nt][1] + b1);
            unsigned short pb = f2_to_e4m3x2(acc[mt][nt][2] + b0, acc[mt][nt][3] + b1);
            t8[c * 80 + r]           = (uint8_t)(pa & 0xff);
            t8[(c + 1) * 80 + r]     = (uint8_t)(pa >> 8);
            t8[c * 80 + r + 8]       = (uint8_t)(pb & 0xff);
            t8[(c + 1) * 80 + r + 8] = (uint8_t)(pb >> 8);
        }
    }
    __syncthreads();

    int bb = row0 / NN;
    int jj = row0 % NN;
    uint8_t* vt = g_v8t + (long)bb * CC * NN;
#pragma unroll
    for (int p = 0; p < 4; p++) {
        int e = tid + p * 256;
        int c = e >> 2, j16 = (e & 3) * 16;
        uint4 v4 = *(uint4*)(sm + VK_T_OFF + c * 80 + j16);
        *(uint4*)&vt[(long)c * NN + jj + j16] = v4;
    }
}

// ---------------------------------------------------------------------------
// Kernel 2: E -> w = exp(e) (fp16, coalesced via smem staging) + 1/rowsum.
//  32 i-rows per CTA, 128 threads, j-tiles of 128, 3-stage cp.async.
// ---------------------------------------------------------------------------
#define SK_Q_OFF  0
#define SK_K_OFF  2560
#define SK_KSTG   10240
#define SK_SR_OFF 33280                  // 32 x 4 f32 (512)
#define SK_W_OFF  33792                  // 32 x 272 half staging (8704)
__global__ void __launch_bounds__(128) expE_kernel()
{
    __shared__ __align__(16) char sm[42496];
    const uint32_t sb = smem_u32(sm);
    int tid = threadIdx.x, lane = tid & 31, w = tid >> 5;
    int b = blockIdx.y, i0 = blockIdx.x * 32;
    const __half* qg = g_qh + ((long)b * NN + i0) * DD;
    const __half* kg = g_kh + (long)b * NN * DD;
    __half* wgl = g_w + ((long)b * NN + i0) * NN;

    {
        int r = tid >> 2, ch = tid & 3;
        *(uint4*)(sm + SK_Q_OFF + r * 80 + ch * 16) = *(const uint4*)(qg + r * DD + ch * 8);
    }
    {
        uint32_t kst = sb + SK_K_OFF;
#pragma unroll
        for (int p = 0; p < 4; p++) {
            int idx = tid + p * 128;
            int r = idx >> 2, ch = idx & 3;
            CP16(kst + r * 80 + ch * 16, kg + r * DD + ch * 8);
        }
        CP_COMMIT();
    }
    __syncthreads();

    uint32_t qf[2][2][4];
#pragma unroll
    for (int mt = 0; mt < 2; mt++) {
        uint32_t base = sb + SK_Q_OFF
            + (mt * 16 + (lane & 7) + ((lane >> 3) & 1) * 8) * 80 + (lane >> 4) * 16;
        ldsm4(qf[mt][0], base);
        ldsm4(qf[mt][1], base + 32);
    }

    float s[4] = {0.f, 0.f, 0.f, 0.f};
    for (int t = 0; t < 32; t++) {
        if (t + 1 < 32) {
            uint32_t kst = sb + SK_K_OFF + ((t + 1) % 3) * SK_KSTG;
            const __half* src = kg + (t + 1) * 128 * DD;
#pragma unroll
            for (int p = 0; p < 4; p++) {
                int idx = tid + p * 128;
                int r = idx >> 2, ch = idx & 3;
                CP16(kst + r * 80 + ch * 16, src + r * DD + ch * 8);
            }
        }
        CP_COMMIT();
        CP_WAIT(1);
        __syncthreads();

        uint32_t kst = sb + SK_K_OFF + (t % 3) * SK_KSTG;
        uint32_t bbase = kst + (w * 32 + (lane & 7)) * 80 + (lane >> 3) * 16;
#pragma unroll
        for (int nt = 0; nt < 4; nt++) {
            uint32_t bf[4];
            ldsm4(bf, bbase + nt * 8 * 80);
            int col = w * 32 + nt * 8 + ((lane & 3) << 1);
#pragma unroll
            for (int mt = 0; mt < 2; mt++) {
                float c[4] = {0.f, 0.f, 0.f, 0.f};
                mma_f16(c, qf[mt][0], bf[0], bf[1]);
                mma_f16(c, qf[mt][1], bf[2], bf[3]);
                float e0 = __expf(c[0]), e1 = __expf(c[1]);
                float e2 = __expf(c[2]), e3 = __expf(c[3]);
                s[mt * 2]     += e0 + e1;
                s[mt * 2 + 1] += e2 + e3;
                int er = mt * 16 + (lane >> 2);
                *(__half2*)(sm + SK_W_OFF + er * 272 + col * 2) =
                    __floats2half2_rn(e0, e1);
                *(__half2*)(sm + SK_W_OFF + (er + 8) * 272 + col * 2) =
                    __floats2half2_rn(e2, e3);
            }
        }
        __syncthreads();
        // coalesced store: 32 rows x 256B
        {
            const long j0 = (long)t * 128;
#pragma unroll
            for (int p = 0; p < 4; p++) {
                int e = tid + p * 128;
                int row = e >> 4, ch = e & 15;
                uint4 v = *(uint4*)(sm + SK_W_OFF + row * 272 + ch * 16);
                *(uint4*)&wgl[(long)row * NN + j0 + ch * 8] = v;
            }
        }
    }
#pragma unroll
    for (int k = 0; k < 4; k++) {
        s[k] += __shfl_xor_sync(0xffffffffu, s[k], 1);
        s[k] += __shfl_xor_sync(0xffffffffu, s[k], 2);
    }
    float* sred = (float*)(sm + SK_SR_OFF);
    if ((lane & 3) == 0) {
        int r0 = lane >> 2;
        sred[(r0     ) * 4 + w] = s[0];
        sred[(r0 + 8 ) * 4 + w] = s[1];
        sred[(r0 + 16) * 4 + w] = s[2];
        sred[(r0 + 24) * 4 + w] = s[3];
    }
    __syncthreads();
    if (tid < 32) {
        float tot = sred[tid * 4] + sred[tid * 4 + 1] + sred[tid * 4 + 2] + sred[tid * 4 + 3];
        g_s[b * NN + i0 + tid] = 1.0f / tot;
    }
}

// ---------------------------------------------------------------------------
// Kernel 3: attention from w: att = w*is (staged->coalesced), P' = fp8(att*4096),
//           O += P' @ V^T, y = O*gamma/PSCALE + x.  No Q/K/E/exp here.
// ---------------------------------------------------------------------------
__global__ void __launch_bounds__(256, 2) attn_kernel(
    const float* __restrict__ x, const float* __restrict__ gamma,
    float* __restrict__ att_out, float* __restrict__ y)
{
    extern __shared__ __align__(16) char smem[];
    const uint32_t sb = smem_u32(smem);
    const int tid  = threadIdx.x;
    const int lane = tid & 31, w = tid >> 5;
    const int wi = w & 3, wj = w >> 2;
    const int avi = w & 1, avc = w >> 1;

    const int b  = blockIdx.y;
    const int i0 = blockIdx.x * 64;

    const __half*  wgl = g_w + ((long)b * NN + i0) * NN;
    const uint8_t* vtg = g_v8t + (long)b * CC * NN;

    if (tid < 64)
        ((float*)(smem + SS_OFF))[tid] = g_s[(long)b * NN + i0 + tid];

    // prolog prefetch: stages 0,1 of {W, V}
#pragma unroll
    for (int st = 0; st < 2; st++) {
        uint32_t wst = sb + W_OFF + st * W_STAGE;
#pragma unroll
        for (int p = 0; p < 2; p++) {
            int idx = tid + p * 256;
            int r = idx >> 3, ch = idx & 7;
            CP16(wst + r * 144 + ch * 16, wgl + (long)r * NN + st * 64 + ch * 8);
        }
        uint32_t vst = sb + V_OFF + st * V_STAGE;
        const uint8_t* vsrc = vtg + st * 64;
#pragma unroll
        for (int p = 0; p < 4; p++) {
            int idx = tid + p * 256;
            int c = idx >> 2, ch = idx & 3;
            CP16(vst + c * 80 + ch * 16, vsrc + (long)c * NN + ch * 16);
        }
        CP_COMMIT();
    }
    __syncthreads();

    const float is0 = ((const float*)(smem + SS_OFF))[wi * 16 + (lane >> 2)];
    const float is1 = ((const float*)(smem + SS_OFF))[wi * 16 + (lane >> 2) + 8];

    float acc[2][8][4];
#pragma unroll
    for (int mt = 0; mt < 2; mt++)
#pragma unroll
        for (int nt = 0; nt < 8; nt++)
#pragma unroll
            for (int u = 0; u < 4; u++) acc[mt][nt][u] = 0.f;

    float* ab = att_out ? att_out + ((long)b * NN + i0) * NN : (float*)0;
    const int er0 = wi * 16 + (lane >> 2);
    const int colb = wj * 32 + ((lane & 3) << 1);
    float* att_s = (float*)(smem + ATT_OFF);

    for (int t = 0; t < 64; t++) {
        const int j0 = t * 64;
        CP_WAIT(1);
        __syncthreads();

        // ---- phase A: w -> att_s (f32) + P' (fp8) ----
        {
            const char* wp = smem + W_OFF + (t % 3) * W_STAGE;
#pragma unroll
            for (int nt = 0; nt < 4; nt++) {
                int col = colb + nt * 8;
                __half2 h0 = *(const __half2*)(wp + er0 * 144 + col * 2);
                __half2 h1 = *(const __half2*)(wp + (er0 + 8) * 144 + col * 2);
                float2 f0 = __half22float2(h0);
                float2 f1 = __half22float2(h1);
                float a0 = f0.x * is0, a1 = f0.y * is0;
                float a2 = f1.x * is1, a3 = f1.y * is1;
                *(unsigned short*)(smem + P_OFF + er0 * 80 + col) =
                    f2_to_e4m3x2(a0 * PSCALE, a1 * PSCALE);
                *(unsigned short*)(smem + P_OFF + (er0 + 8) * 80 + col) =
                    f2_to_e4m3x2(a2 * PSCALE, a3 * PSCALE);
                if (ab) {
                    *(float2*)&att_s[er0 * ATT_STRIDE + col]       = make_float2(a0, a1);
                    *(float2*)&att_s[(er0 + 8) * ATT_STRIDE + col] = make_float2(a2, a3);
                }
            }
        }
        __syncthreads();

        // ---- att coalesced store: warp = 2 rows x 256B, STG.128 streaming ----
        if (ab) {
#pragma unroll
            for (int k = 0; k < 4; k++) {
                int row = w * 2 + (lane >> 4) + k * 16;
                int c4  = (lane & 15) * 4;
                float4 v = *(const float4*)&att_s[row * ATT_STRIDE + c4];
                __stcs((float4*)&ab[(long)row * NN + j0 + c4], v);
            }
        }

        // ---- AV(t): O += P'(t) @ V^T(stage t%3) ----
        {
            uint32_t vst = sb + V_OFF + (t % 3) * V_STAGE;
            uint32_t pA  = sb + P_OFF
                + (avi * 32 + (lane & 7) + ((lane >> 3) & 1) * 8) * 80
                + ((lane >> 4) & 1) * 16;
            uint32_t af[2][2][4];
#pragma unroll
            for (int mt = 0; mt < 2; mt++) {
                ldsm4(af[mt][0], pA + mt * 16 * 80);
                ldsm4(af[mt][1], pA + mt * 16 * 80 + 32);
            }
#pragma unroll
            for (int kk = 0; kk < 2; kk++) {
#pragma unroll
                for (int ntg = 0; ntg < 4; ntg++) {
                    uint32_t bv[4];
                    uint32_t baddr = vst
                        + (avc * 64 + ntg * 16 + (lane & 7) + ((lane >> 4) & 1) * 8) * 80
                        + ((lane >> 3) & 1) * 16 + kk * 32;
                    ldsm4(bv, baddr);
                    mma_f8(acc[0][ntg * 2],     af[0][kk], bv[0], bv[1]);
                    mma_f8(acc[0][ntg * 2 + 1], af[0][kk], bv[2], bv[3]);
                    mma_f8(acc[1][ntg * 2],     af[1][kk], bv[0], bv[1]);
                    mma_f8(acc[1][ntg * 2 + 1], af[1][kk], bv[2], bv[3]);
                }
            }
        }

        // ---- prefetch W(t+2), V(t+2) ----
        if (t + 2 < 64) {
            uint32_t wst = sb + W_OFF + ((t + 2) % 3) * W_STAGE;
            const __half* wsrc = wgl + (t + 2) * 64;
#pragma unroll
            for (int p = 0; p < 2; p++) {
                int idx = tid + p * 256;
                int r = idx >> 3, ch = idx & 7;
                CP16(wst + r * 144 + ch * 16, wsrc + (long)r * NN + ch * 8);
            }
            uint32_t vst = sb + V_OFF + ((t + 2) % 3) * V_STAGE;
            const uint8_t* vsrc = vtg + (t + 2) * 64;
#pragma unroll
            for (int p = 0; p < 4; p++) {
                int idx = tid + p * 256;
                int c = idx >> 2, ch = idx & 3;
                CP16(vst + c * 80 + ch * 16, vsrc + (long)c * NN + ch * 16);
            }
        }
        CP_COMMIT();
    }

    // ---- epilogue: y = acc*(gamma/PSCALE) + x ----
    const float g = gamma[0] * (1.0f / PSCALE);
    const float* xb = x + ((long)b * NN + i0) * CC;
    float* yb = y + ((long)b * NN + i0) * CC;
#pragma unroll
    for (int mt = 0; mt < 2; mt++) {
        int r0 = avi * 32 + mt * 16 + (lane >> 2);
#pragma unroll
        for (int nt = 0; nt < 8; nt++) {
            int c = avc * 64 + nt * 8 + ((lane & 3) << 1);
            float2 x0 = *(const float2*)&xb[(long)r0 * CC + c];
            float2 x1 = *(const float2*)&xb[(long)(r0 + 8) * CC + c];
            float2 o0, o1;
            o0.x = acc[mt][nt][0] * g + x0.x;  o0.y = acc[mt][nt][1] * g + x0.y;
            o1.x = acc[mt][nt][2] * g + x1.x;  o1.y = acc[mt][nt][3] * g + x1.y;
            *(float2*)&yb[(long)r0 * CC + c]       = o0;
            *(float2*)&yb[(long)(r0 + 8) * CC + c] = o1;
        }
    }
}

// ---------------------------------------------------------------------------
extern "C" void kernel_launch(void* const* d_in, const int* in_sizes, int n_in,
                              void* d_out, int out_size)
{
    const float* x     = (const float*)d_in[0];
    const float* Wq    = (const float*)d_in[1];
    const float* bq    = (const float*)d_in[2];
    const float* Wk    = (const float*)d_in[3];
    const float* bk    = (const float*)d_in[4];
    const float* Wv    = (const float*)d_in[5];
    const float* bv    = (const float*)d_in[6];
    const float* gamma = (const float*)d_in[7];
    float* y = (float*)d_out;

    const long ATT_E = (long)BN * NN * NN;
    float* att_out = 0;
    if ((long)out_size == (long)OUT_E + ATT_E) att_out = y + OUT_E;

    cudaFuncSetAttribute(attn_kernel, cudaFuncAttributeMaxDynamicSharedMemorySize,
                         SMEM_ATTN);

    qkv16_kernel<<<BN * NN / 64, 256>>>(x, Wq, bq, Wk, bk, Wv, bv);
    expE_kernel<<<dim3(NN / 32, BN), 128>>>();
    attn_kernel<<<dim3(NN / 64, BN), 256, SMEM_ATTN>>>(x, gamma, att_out, y);
}

// round 15
// speedup vs baseline: 1.3695x; 1.0479x over previous
#include <cuda_runtime.h>
#include <cuda_fp16.h>
#include <cuda_fp8.h>
#include <cstdint>

#define BN 4
#define NN 4096
#define CC 256
#define DD 32
#define OUT_E (4*64*64*256)
#define PSCALE 4096.0f

// Scratch (device globals -> no allocations)
__device__ __half   g_qh  [BN * NN * DD];
__device__ __half   g_kh  [BN * NN * DD];
__device__ uint8_t  g_v8t [(long)BN * CC * NN];  // V transposed: [b][c][j], e4m3
__device__ float    g_s   [BN * NN];             // 1/rowsum
__device__ __half   g_wvh [CC * CC];             // Wv^T fp16: [n][kk]
__device__ __half   g_wqkh[64 * CC];             // [Wq|Wk]^T fp16: [n][kk]

// ---------------------------------------------------------------------------
// helpers
// ---------------------------------------------------------------------------
__device__ __forceinline__ uint32_t smem_u32(const void* p) {
    return (uint32_t)__cvta_generic_to_shared(p);
}
__device__ __forceinline__ void ldsm4(uint32_t* r, uint32_t addr) {
    asm volatile("ldmatrix.sync.aligned.m8n8.x4.shared.b16 {%0,%1,%2,%3}, [%4];"
                 : "=r"(r[0]), "=r"(r[1]), "=r"(r[2]), "=r"(r[3]) : "r"(addr));
}
__device__ __forceinline__ void mma_f16(float* c, const uint32_t* a,
                                        uint32_t b0, uint32_t b1) {
    asm volatile("mma.sync.aligned.m16n8k16.row.col.f32.f16.f16.f32 "
                 "{%0,%1,%2,%3}, {%4,%5,%6,%7}, {%8,%9}, {%0,%1,%2,%3};"
                 : "+f"(c[0]), "+f"(c[1]), "+f"(c[2]), "+f"(c[3])
                 : "r"(a[0]), "r"(a[1]), "r"(a[2]), "r"(a[3]), "r"(b0), "r"(b1));
}
__device__ __forceinline__ void mma_f8(float* c, const uint32_t* a,
                                       uint32_t b0, uint32_t b1) {
    asm volatile("mma.sync.aligned.m16n8k32.row.col.f32.e4m3.e4m3.f32 "
                 "{%0,%1,%2,%3}, {%4,%5,%6,%7}, {%8,%9}, {%0,%1,%2,%3};"
                 : "+f"(c[0]), "+f"(c[1]), "+f"(c[2]), "+f"(c[3])
                 : "r"(a[0]), "r"(a[1]), "r"(a[2]), "r"(a[3]), "r"(b0), "r"(b1));
}
__device__ __forceinline__ unsigned short f2_to_e4m3x2(float lo, float hi) {
    return (unsigned short)__nv_cvt_float2_to_fp8x2(make_float2(lo, hi),
                                                    __NV_SATFINITE, __NV_E4M3);
}
#define CP16(dst, src) \
    asm volatile("cp.async.cg.shared.global [%0], [%1], 16;" :: "r"(dst), "l"(src))
#define CP_COMMIT() asm volatile("cp.async.commit_group;" ::: "memory")
#define CP_WAIT(n)  asm volatile("cp.async.wait_group %0;" :: "n"(n) : "memory")

// ---------------------------------------------------------------------------
// Kernel 0: one-time weight transpose + fp16 cvt (Wv, [Wq|Wk])
// ---------------------------------------------------------------------------
__global__ void __launch_bounds__(256) wprep_kernel(
    const float* __restrict__ Wq, const float* __restrict__ Wk,
    const float* __restrict__ Wv)
{
    int n  = blockIdx.x;      // 0..255
    int kk = threadIdx.x;     // 0..255
    g_wvh[n * CC + kk] = __float2half_rn(Wv[(long)kk * CC + n]);
    if (n < 64) {
        float v = (n < 32) ? Wq[(long)kk * DD + n] : Wk[(long)kk * DD + (n - 32)];
        g_wqkh[n * CC + kk] = __float2half_rn(v);
    }
}

// ---------------------------------------------------------------------------
// Kernel 1: fused q,k,v projections via fp16 HMMA.
//  W tiles staged via cp.async from pre-transposed fp16 globals, double-buffered.
// ---------------------------------------------------------------------------
#define VK_X_OFF   0         // 64 x 80                 (5120)
#define VK_W_OFF   5120      // 2 bufs x 256 x 80       (40960)
#define VK_QK_OFF  46080     // 2 bufs x 64 x 80        (10240)
#define VK_T_OFF   5120      // aliases W buf0 after last mma
#define VK_W_STG   20480
#define VK_QK_STG  5120
#define QKV_SMEM   56320
__global__ void __launch_bounds__(256, 2) qkv16_kernel(
    const float* __restrict__ x,
    const float* __restrict__ bq, const float* __restrict__ bk,
    const float* __restrict__ bv)
{
    extern __shared__ __align__(16) char sm[];
    const uint32_t sb = smem_u32(sm);
    int row0 = blockIdx.x * 64;
    int tid  = threadIdx.x;
    int lane = tid & 31, warp = tid >> 5;
    int wm = warp & 1, wn = warp >> 1;

    float acc[2][8][4];
    float aqk[2][2][4];
#pragma unroll
    for (int mt = 0; mt < 2; mt++) {
#pragma unroll
        for (int nt = 0; nt < 8; nt++)
#pragma unroll
            for (int u = 0; u < 4; u++) acc[mt][nt][u] = 0.f;
#pragma unroll
        for (int nt = 0; nt < 2; nt++)
#pragma unroll
            for (int u = 0; u < 4; u++) aqk[mt][nt][u] = 0.f;
    }

    // prolog: W(0) -> buf 0
    {
#pragma unroll
        for (int p = 0; p < 4; p++) {
            int idx = tid + p * 256;
            int n = idx >> 2, c = idx & 3;
            CP16(sb + VK_W_OFF + n * 80 + c * 16, g_wvh + n * CC + c * 8);
        }
        {
            int n = tid >> 2, c = tid & 3;
            CP16(sb + VK_QK_OFF + n * 80 + c * 16, g_wqkh + n * CC + c * 8);
        }
        CP_COMMIT();
    }

    for (int kcI = 0; kcI < 8; kcI++) {
        const int kc = kcI * 32;
        __syncthreads();
        // x fp32 -> fp16 smem tile [64 rows][32 k], stride 80B
        {
            int r = tid >> 2, kq = (tid & 3) * 8;
            float4 xa = *(const float4*)&x[(long)(row0 + r) * CC + kc + kq];
            float4 xb = *(const float4*)&x[(long)(row0 + r) * CC + kc + kq + 4];
            __half2 h[4];
            h[0] = __floats2half2_rn(xa.x, xa.y);
            h[1] = __floats2half2_rn(xa.z, xa.w);
            h[2] = __floats2half2_rn(xb.x, xb.y);
            h[3] = __floats2half2_rn(xb.z, xb.w);
            *(uint4*)(sm + VK_X_OFF + r * 80 + kq * 2) = *(uint4*)h;
        }
        // prefetch W(kcI+1) into alternate buf
        if (kcI + 1 < 8) {
            const int kcn = kc + 32;
            const int bsel = (kcI + 1) & 1;
#pragma unroll
            for (int p = 0; p < 4; p++) {
                int idx = tid + p * 256;
                int n = idx >> 2, c = idx & 3;
                CP16(sb + VK_W_OFF + bsel * VK_W_STG + n * 80 + c * 16,
                     g_wvh + n * CC + kcn + c * 8);
            }
            {
                int n = tid >> 2, c = tid & 3;
                CP16(sb + VK_QK_OFF + bsel * VK_QK_STG + n * 80 + c * 16,
                     g_wqkh + n * CC + kcn + c * 8);
            }
        }
        CP_COMMIT();
        CP_WAIT(1);
        __syncthreads();

        const uint32_t wbuf  = sb + VK_W_OFF + (kcI & 1) * VK_W_STG;
        const uint32_t qkbuf = sb + VK_QK_OFF + (kcI & 1) * VK_QK_STG;

        uint32_t af[2][2][4];
#pragma unroll
        for (int mt = 0; mt < 2; mt++) {
            uint32_t abase = sb + VK_X_OFF
                + (wm * 32 + mt * 16 + (lane & 7) + ((lane >> 3) & 1) * 8) * 80
                + (lane >> 4) * 16;
            ldsm4(af[mt][0], abase);
            ldsm4(af[mt][1], abase + 32);
        }
#pragma unroll
        for (int nt = 0; nt < 8; nt++) {
            uint32_t bf[4];
            uint32_t bbase = wbuf
                + (wn * 64 + nt * 8 + (lane & 7)) * 80 + (lane >> 3) * 16;
            ldsm4(bf, bbase);
            mma_f16(acc[0][nt], af[0][0], bf[0], bf[1]);
            mma_f16(acc[0][nt], af[0][1], bf[2], bf[3]);
            mma_f16(acc[1][nt], af[1][0], bf[0], bf[1]);
            mma_f16(acc[1][nt], af[1][1], bf[2], bf[3]);
        }
#pragma unroll
        for (int nt = 0; nt < 2; nt++) {
            uint32_t bf[4];
            uint32_t bbase = qkbuf
                + (wn * 16 + nt * 8 + (lane & 7)) * 80 + (lane >> 3) * 16;
            ldsm4(bf, bbase);
            mma_f16(aqk[0][nt], af[0][0], bf[0], bf[1]);
            mma_f16(aqk[0][nt], af[0][1], bf[2], bf[3]);
            mma_f16(aqk[1][nt], af[1][0], bf[0], bf[1]);
            mma_f16(aqk[1][nt], af[1][1], bf[2], bf[3]);
        }
    }

    // q/k epilogue
#pragma unroll
    for (int mt = 0; mt < 2; mt++) {
#pragma unroll
        for (int nt = 0; nt < 2; nt++) {
            int r = wm * 32 + mt * 16 + (lane >> 2);
            int gcol = wn * 16 + nt * 8 + ((lane & 3) << 1);
            int isq = gcol < 32;
            int cc = isq ? gcol : gcol - 32;
            const float* bb_ = isq ? bq : bk;
            __half* dst = isq ? g_qh : g_kh;
            float b0 = bb_[cc], b1 = bb_[cc + 1];
            *(__half2*)&dst[(long)(row0 + r) * DD + cc] =
                __floats2half2_rn(aqk[mt][nt][0] + b0, aqk[mt][nt][1] + b1);
            *(__half2*)&dst[(long)(row0 + r + 8) * DD + cc] =
                __floats2half2_rn(aqk[mt][nt][2] + b0, aqk[mt][nt][3] + b1);
        }
    }

    __syncthreads();   // all mma ldsm done -> W buf0 reusable as T

    uint8_t* t8 = (uint8_t*)(sm + VK_T_OFF);
#pragma unroll
    for (int mt = 0; mt < 2; mt++) {
        int r = wm * 32 + mt * 16 + (lane >> 2);
#pragma unroll
        for (int nt = 0; nt < 8; nt++) {
            int c = wn * 64 + nt * 8 + ((lane & 3) << 1);
            float b0 = bv[c], b1 = bv[c + 1];
            unsigned short pa = f2_to_e4m3x2(acc[mt][nt][0] + b0, acc[mt][nt][1] + b1);
            unsigned short pb = f2_to_e4m3x2(acc[mt][nt][2] + b0, acc[mt][nt][3] + b1);
            t8[c * 80 + r]           = (uint8_t)(pa & 0xff);
            t8[(c + 1) * 80 + r]     = (uint8_t)(pa >> 8);
            t8[c * 80 + r + 8]       = (uint8_t)(pb & 0xff);
            t8[(c + 1) * 80 + r + 8] = (uint8_t)(pb >> 8);
        }
    }
    __syncthreads();

    int bb = row0 / NN;
    int jj = row0 % NN;
    uint8_t* vt = g_v8t + (long)bb * CC * NN;
#pragma unroll
    for (int p = 0; p < 4; p++) {
        int e = tid + p * 256;
        int c = e >> 2, j16 = (e & 3) * 16;
        uint4 v4 = *(uint4*)(sm + VK_T_OFF + c * 80 + j16);
        *(uint4*)&vt[(long)c * NN + jj + j16] = v4;
    }
}

// ---------------------------------------------------------------------------
// Kernel 2: row sums of exp(Q.K^T) -> g_s = 1/s (R12 verbatim).
// ---------------------------------------------------------------------------
#define SK_Q_OFF  0
#define SK_K_OFF  2560
#define SK_KSTG   10240
#define SK_SR_OFF (2560 + 3*10240)
__global__ void __launch_bounds__(128) sum_kernel()
{
    __shared__ __align__(16) char sm[33792];
    const uint32_t sb = smem_u32(sm);
    int tid = threadIdx.x, lane = tid & 31, w = tid >> 5;
    int b = blockIdx.y, i0 = blockIdx.x * 32;
    const __half* qg = g_qh + ((long)b * NN + i0) * DD;
    const __half* kg = g_kh + (long)b * NN * DD;

    {
        int r = tid >> 2, ch = tid & 3;
        *(uint4*)(sm + SK_Q_OFF + r * 80 + ch * 16) = *(const uint4*)(qg + r * DD + ch * 8);
    }
    {
        uint32_t kst = sb + SK_K_OFF;
#pragma unroll
        for (int p = 0; p < 4; p++) {
            int idx = tid + p * 128;
            int r = idx >> 2, ch = idx & 3;
            CP16(kst + r * 80 + ch * 16, kg + r * DD + ch * 8);
        }
        CP_COMMIT();
    }
    __syncthreads();

    uint32_t qf[2][2][4];
#pragma unroll
    for (int mt = 0; mt < 2; mt++) {
        uint32_t base = sb + SK_Q_OFF
            + (mt * 16 + (lane & 7) + ((lane >> 3) & 1) * 8) * 80 + (lane >> 4) * 16;
        ldsm4(qf[mt][0], base);
        ldsm4(qf[mt][1], base + 32);
    }

    float s[4] = {0.f, 0.f, 0.f, 0.f};
    for (int t = 0; t < 32; t++) {
        if (t + 1 < 32) {
            uint32_t kst = sb + SK_K_OFF + ((t + 1) % 3) * SK_KSTG;
            const __half* src = kg + (t + 1) * 128 * DD;
#pragma unroll
            for (int p = 0; p < 4; p++) {
                int idx = tid + p * 128;
                int r = idx >> 2, ch = idx & 3;
                CP16(kst + r * 80 + ch * 16, src + r * DD + ch * 8);
            }
        }
        CP_COMMIT();
        CP_WAIT(1);
        __syncthreads();

        uint32_t kst = sb + SK_K_OFF + (t % 3) * SK_KSTG;
        uint32_t bbase = kst + (w * 32 + (lane & 7)) * 80 + (lane >> 3) * 16;
#pragma unroll
        for (int nt = 0; nt < 4; nt++) {
            uint32_t bf[4];
            ldsm4(bf, bbase + nt * 8 * 80);
#pragma unroll
            for (int mt = 0; mt < 2; mt++) {
                float c[4] = {0.f, 0.f, 0.f, 0.f};
                mma_f16(c, qf[mt][0], bf[0], bf[1]);
                mma_f16(c, qf[mt][1], bf[2], bf[3]);
                s[mt * 2]     += __expf(c[0]) + __expf(c[1]);
                s[mt * 2 + 1] += __expf(c[2]) + __expf(c[3]);
            }
        }
    }
#pragma unroll
    for (int k = 0; k < 4; k++) {
        s[k] += __shfl_xor_sync(0xffffffffu, s[k], 1);
        s[k] += __shfl_xor_sync(0xffffffffu, s[k], 2);
    }
    float* sred = (float*)(sm + SK_SR_OFF);
    if ((lane & 3) == 0) {
        int r0 = lane >> 2;
        sred[(r0     ) * 4 + w] = s[0];
        sred[(r0 + 8 ) * 4 + w] = s[1];
        sred[(r0 + 16) * 4 + w] = s[2];
        sred[(r0 + 24) * 4 + w] = s[3];
    }
    __syncthreads();
    if (tid < 32) {
        float tot = sred[tid * 4] + sred[tid * 4 + 1] + sred[tid * 4 + 2] + sred[tid * 4 + 3];
        g_s[b * NN + i0 + tid] = 1.0f / tot;
    }
}

// ---------------------------------------------------------------------------
// Kernel 3: attention pass2 (R12 verbatim): E recompute, att staged->coalesced,
//           P' fp8, AV QMMA, epilogue.
// ---------------------------------------------------------------------------
#define Q_OFF     0
#define P_OFF     5120
#define K2_OFF    10240
#define V_OFF     30720
#define ATT_OFF   92160
#define SS_OFF    110592
#define SMEM_ATTN 110848
#define V_STAGE   20480
#define K2_STAGE  5120
#define ATT_STRIDE 72
__global__ void __launch_bounds__(256, 2) attn_kernel(
    const float* __restrict__ x, const float* __restrict__ gamma,
    float* __restrict__ att_out, float* __restrict__ y)
{
    extern __shared__ __align__(16) char smem[];
    const uint32_t sb = smem_u32(smem);
    const int tid  = threadIdx.x;
    const int lane = tid & 31, w = tid >> 5;
    const int wi = w & 3, wj = w >> 2;
    const int avi = w & 1, avc = w >> 1;

    const int b  = blockIdx.y;
    const int i0 = blockIdx.x * 64;

    const __half*  qg  = g_qh + ((long)b * NN + i0) * DD;
    const __half*  kg  = g_kh + (long)b * NN * DD;
    const uint8_t* vtg = g_v8t + (long)b * CC * NN;

    {
        int r = tid >> 2, ch = tid & 3;
        *(uint4*)(smem + Q_OFF + r * 80 + ch * 16) =
            *(const uint4*)(qg + r * DD + ch * 8);
    }
    if (tid < 64)
        ((float*)(smem + SS_OFF))[tid] = g_s[(long)b * NN + i0 + tid];

    {
#pragma unroll
        for (int st = 0; st < 2; st++) {
            uint32_t vst = sb + V_OFF + st * V_STAGE;
            const uint8_t* vsrc = vtg + st * 64;
#pragma unroll
            for (int p = 0; p < 4; p++) {
                int idx = tid + p * 256;
                int c = idx >> 2, ch = idx & 3;
                CP16(vst + c * 80 + ch * 16, vsrc + (long)c * NN + ch * 16);
            }
            int r = tid >> 2, ch = tid & 3;
            CP16(sb + K2_OFF + st * K2_STAGE + r * 80 + ch * 16,
                 kg + (st * 64 + r) * DD + ch * 8);
            CP_COMMIT();
        }
    }
    __syncthreads();

    uint32_t qf[2][4];
    {
        uint32_t base = sb + Q_OFF
            + (wi * 16 + (lane & 7) + ((lane >> 3) & 1) * 8) * 80
            + (lane >> 4) * 16;
        ldsm4(qf[0], base);
        ldsm4(qf[1], base + 32);
    }
    const float is0 = ((const float*)(smem + SS_OFF))[wi * 16 + (lane >> 2)];
    const float is1 = ((const float*)(smem + SS_OFF))[wi * 16 + (lane >> 2) + 8];

    float acc[2][8][4];
#pragma unroll
    for (int mt = 0; mt < 2; mt++)
#pragma unroll
        for (int nt = 0; nt < 8; nt++)
#pragma unroll
            for (int u = 0; u < 4; u++) acc[mt][nt][u] = 0.f;

    float* ab = att_out ? att_out + ((long)b * NN + i0) * NN : (float*)0;
    const int er0 = wi * 16 + (lane >> 2);
    float* att_s = (float*)(smem + ATT_OFF);

    for (int t = 0; t < 64; t++) {
        const int j0 = t * 64;
        CP_WAIT(1);
        __syncthreads();

        {
            uint32_t k2t = sb + K2_OFF + (t & 3) * K2_STAGE;
            uint32_t ebase = k2t + (wj * 32 + (lane & 7)) * 80 + (lane >> 3) * 16;
#pragma unroll
            for (int nt = 0; nt < 4; nt++) {
                uint32_t bf[4];
                ldsm4(bf, ebase + nt * 8 * 80);
                float c[4] = {0.f, 0.f, 0.f, 0.f};
                mma_f16(c, qf[0], bf[0], bf[1]);
                mma_f16(c, qf[1], bf[2], bf[3]);
                float a0 = __expf(c[0]) * is0, a1 = __expf(c[1]) * is0;
                float a2 = __expf(c[2]) * is1, a3 = __expf(c[3]) * is1;
                int col = wj * 32 + nt * 8 + ((lane & 3) << 1);
                *(unsigned short*)(smem + P_OFF + er0 * 80 + col) =
                    f2_to_e4m3x2(a0 * PSCALE, a1 * PSCALE);
                *(unsigned short*)(smem + P_OFF + (er0 + 8) * 80 + col) =
                    f2_to_e4m3x2(a2 * PSCALE, a3 * PSCALE);
                if (ab) {
                    *(float2*)&att_s[er0 * ATT_STRIDE + col]       = make_float2(a0, a1);
                    *(float2*)&att_s[(er0 + 8) * ATT_STRIDE + col] = make_float2(a2, a3);
                }
            }
        }
        __syncthreads();

        if (ab) {
#pragma unroll
            for (int k = 0; k < 4; k++) {
                int row = w * 2 + (lane >> 4) + k * 16;
                int c4  = (lane & 15) * 4;
                float4 v = *(const float4*)&att_s[row * ATT_STRIDE + c4];
                __stcs((float4*)&ab[(long)row * NN + j0 + c4], v);
            }
        }

        {
            uint32_t vst = sb + V_OFF + (t % 3) * V_STAGE;
            uint32_t pA  = sb + P_OFF
                + (avi * 32 + (lane & 7) + ((lane >> 3) & 1) * 8) * 80
                + ((lane >> 4) & 1) * 16;
            uint32_t af[2][2][4];
#pragma unroll
            for (int mt = 0; mt < 2; mt++) {
                ldsm4(af[mt][0], pA + mt * 16 * 80);
                ldsm4(af[mt][1], pA + mt * 16 * 80 + 32);
            }
#pragma unroll
            for (int kk = 0; kk < 2; kk++) {
#pragma unroll
                for (int ntg = 0; ntg < 4; ntg++) {
                    uint32_t bv[4];
                    uint32_t baddr = vst
                        + (avc * 64 + ntg * 16 + (lane & 7) + ((lane >> 4) & 1) * 8) * 80
                        + ((lane >> 3) & 1) * 16 + kk * 32;
                    ldsm4(bv, baddr);
                    mma_f8(acc[0][ntg * 2],     af[0][kk], bv[0], bv[1]);
                    mma_f8(acc[0][ntg * 2 + 1], af[0][kk], bv[2], bv[3]);
                    mma_f8(acc[1][ntg * 2],     af[1][kk], bv[0], bv[1]);
                    mma_f8(acc[1][ntg * 2 + 1], af[1][kk], bv[2], bv[3]);
                }
            }
        }

        if (t + 2 < 64) {
            uint32_t vst = sb + V_OFF + ((t + 2) % 3) * V_STAGE;
            const uint8_t* vsrc = vtg + (t + 2) * 64;
#pragma unroll
            for (int p = 0; p < 4; p++) {
                int idx = tid + p * 256;
                int c = idx >> 2, ch = idx & 3;
                CP16(vst + c * 80 + ch * 16, vsrc + (long)c * NN + ch * 16);
            }
            uint32_t k2t = sb + K2_OFF + ((t + 2) & 3) * K2_STAGE;
            const __half* ksrc = kg + (t + 2) * 64 * DD;
            int r = tid >> 2, ch = tid & 3;
            CP16(k2t + r * 80 + ch * 16, ksrc + r * DD + ch * 8);
        }
        CP_COMMIT();
    }

    const float g = gamma[0] * (1.0f / PSCALE);
    const float* xb = x + ((long)b * NN + i0) * CC;
    float* yb = y + ((long)b * NN + i0) * CC;
#pragma unroll
    for (int mt = 0; mt < 2; mt++) {
        int r0 = avi * 32 + mt * 16 + (lane >> 2);
#pragma unroll
        for (int nt = 0; nt < 8; nt++) {
            int c = avc * 64 + nt * 8 + ((lane & 3) << 1);
            float2 x0 = *(const float2*)&xb[(long)r0 * CC + c];
            float2 x1 = *(const float2*)&xb[(long)(r0 + 8) * CC + c];
            float2 o0, o1;
            o0.x = acc[mt][nt][0] * g + x0.x;  o0.y = acc[mt][nt][1] * g + x0.y;
            o1.x = acc[mt][nt][2] * g + x1.x;  o1.y = acc[mt][nt][3] * g + x1.y;
            *(float2*)&yb[(long)r0 * CC + c]       = o0;
            *(float2*)&yb[(long)(r0 + 8) * CC + c] = o1;
        }
    }
}

// ---------------------------------------------------------------------------
extern "C" void kernel_launch(void* const* d_in, const int* in_sizes, int n_in,
                              void* d_out, int out_size)
{
    const float* x     = (const float*)d_in[0];
    const float* Wq    = (const float*)d_in[1];
    const float* bq    = (const float*)d_in[2];
    const float* Wk    = (const float*)d_in[3];
    const float* bk    = (const float*)d_in[4];
    const float* Wv    = (const float*)d_in[5];
    const float* bv    = (const float*)d_in[6];
    const float* gamma = (const float*)d_in[7];
    float* y = (float*)d_out;

    const long ATT_E = (long)BN * NN * NN;
    float* att_out = 0;
    if ((long)out_size == (long)OUT_E + ATT_E) att_out = y + OUT_E;

    cudaFuncSetAttribute(qkv16_kernel, cudaFuncAttributeMaxDynamicSharedMemorySize,
                         QKV_SMEM);
    cudaFuncSetAttribute(attn_kernel, cudaFuncAttributeMaxDynamicSharedMemorySize,
                         SMEM_ATTN);

    wprep_kernel<<<256, 256>>>(Wq, Wk, Wv);
    qkv16_kernel<<<BN * NN / 64, 256, QKV_SMEM>>>(x, bq, bk, bv);
    sum_kernel<<<dim3(NN / 32, BN), 128>>>();
    attn_kernel<<<dim3(NN / 64, BN), 256, SMEM_ATTN>>>(x, gamma, att_out, y);
}